// round 9
// baseline (speedup 1.0000x reference)
#include <cuda_runtime.h>
#include <math.h>
#include <stdint.h>

#define N      8192
#define FIN    256
#define FOUT   64
#define ALPHA  0.2f

#define NPROJ  128          // projection blocks (bid < NPROJ)
#define NSCANB 612          // scan blocks (dynamic row queue)
#define NBLK   (NPROJ + NSCANB)   // 740 = 148 * 5  (single wave)
#define TR     64
#define KC     32
#define NCH    (FIN / KC)
#define CAP    384          // neighbor capacity/row (E=32)

// ---------------- scratch (static __device__, allocation-free) --------------
__device__ __align__(16) static float g_fts[N * FOUT];
__device__ __align__(16) static float g_f1[N];
__device__ __align__(16) static float g_f2[N];
__device__ static int g_done;   // proj blocks finished
__device__ static int g_fin;    // scan blocks finished
__device__ static int g_row;    // dynamic row queue head

// shared-memory overlay: proj tile vs scan state never coexist in a block
struct ProjS {
    float xs[TR][KC + 1];
    float ws[KC * FOUT];
};
struct ScanS {
    int   idx[CAP];
    float wt[CAP];
    float part[4 * FOUT];
    float red[8];
    int   woff[8];
    int   total;
    int   row;
    int   ready;
    float Sv;
    float mv;
};

__global__ __launch_bounds__(256, 5) void k_main(
        const float* __restrict__ x,   const float* __restrict__ W,
        const float* __restrict__ adj,
        const float* __restrict__ a1,  const float* __restrict__ b1,
        const float* __restrict__ a2,  const float* __restrict__ b2,
        const float* __restrict__ bias, float* __restrict__ out) {
    __shared__ __align__(16) char smem_raw[sizeof(ProjS) > sizeof(ScanS)
                                           ? sizeof(ProjS) : sizeof(ScanS)];
    const int tid  = threadIdx.x;
    const int lane = tid & 31;
    const int wid  = tid >> 5;

    if (blockIdx.x < NPROJ) {
        // ========================= projection role ==========================
        ProjS& S = *reinterpret_cast<ProjS*>(smem_raw);
        const int row0 = blockIdx.x * TR;
        const int fg = tid & 15, rg = tid >> 4;
        const int f0 = fg * 4,   r0 = rg * 4;
        const int xk = tid & 31, xr0 = tid >> 5;
        const float4* __restrict__ W4 = (const float4*)W;

        float acc[4][4] = {};
#pragma unroll
        for (int c = 0; c < NCH; c++) {
            const int kc = c * KC;
            __syncthreads();
#pragma unroll
            for (int i = 0; i < 8; i++)
                S.xs[xr0 + 8 * i][xk] = x[(size_t)(row0 + xr0 + 8 * i) * FIN + kc + xk];
            {
                float4* ws4 = (float4*)S.ws;
#pragma unroll
                for (int i = 0; i < 2; i++)
                    ws4[tid + i * 256] = W4[kc * 16 + tid + i * 256];
            }
            __syncthreads();
#pragma unroll
            for (int k = 0; k < KC; k++) {
                const float4 wv = *(const float4*)&S.ws[k * FOUT + f0];
                float xr[4];
#pragma unroll
                for (int r = 0; r < 4; r++) xr[r] = S.xs[r0 + r][k];
                const float wf[4] = {wv.x, wv.y, wv.z, wv.w};
#pragma unroll
                for (int r = 0; r < 4; r++)
#pragma unroll
                    for (int j = 0; j < 4; j++)
                        acc[r][j] = fmaf(xr[r], wf[j], acc[r][j]);
            }
        }

#pragma unroll
        for (int r = 0; r < 4; r++) {
            float4 v = make_float4(acc[r][0], acc[r][1], acc[r][2], acc[r][3]);
            *(float4*)&g_fts[(size_t)(row0 + r0 + r) * FOUT + f0] = v;
        }

        const float4 a1v = *(const float4*)&a1[f0];
        const float4 a2v = *(const float4*)&a2[f0];
        float p1[4], p2[4];
#pragma unroll
        for (int r = 0; r < 4; r++) {
            p1[r] = acc[r][0]*a1v.x + acc[r][1]*a1v.y + acc[r][2]*a1v.z + acc[r][3]*a1v.w;
            p2[r] = acc[r][0]*a2v.x + acc[r][1]*a2v.y + acc[r][2]*a2v.z + acc[r][3]*a2v.w;
        }
#pragma unroll
        for (int o = 1; o < 16; o <<= 1) {
#pragma unroll
            for (int r = 0; r < 4; r++) {
                p1[r] += __shfl_xor_sync(0xffffffffu, p1[r], o);
                p2[r] += __shfl_xor_sync(0xffffffffu, p2[r], o);
            }
        }
        if (fg == 0) {
            const float bb1 = __ldg(b1), bb2 = __ldg(b2);
#pragma unroll
            for (int r = 0; r < 4; r++) {
                g_f1[row0 + r0 + r] = p1[r] + bb1;
                g_f2[row0 + r0 + r] = p2[r] + bb2;
            }
        }
        __threadfence();
        __syncthreads();
        if (tid == 0) atomicAdd(&g_done, 1);
        return;
    }

    // =========================== scan role (block per row) ==================
    ScanS& S = *reinterpret_cast<ScanS*>(smem_raw);
    if (tid == 0) S.ready = 0;

    for (;;) {
        if (tid == 0) S.row = atomicAdd(&g_row, 1);
        __syncthreads();
        const int row = S.row;
        if (row >= N) break;

        // ---- phase A: stream full 32KB row, ballot mask, compact ----
        const float4* __restrict__ adjr = (const float4*)(adj + (size_t)row * N);
        float4 av[8];
#pragma unroll
        for (int it = 0; it < 8; it++)
            av[it] = adjr[it * 256 + tid];

        unsigned mymask = 0;
#pragma unroll
        for (int it = 0; it < 8; it++) {
            const unsigned b0 = __ballot_sync(0xffffffffu, av[it].x >= 0.f);
            const unsigned b1 = __ballot_sync(0xffffffffu, av[it].y >= 0.f);
            const unsigned b2 = __ballot_sync(0xffffffffu, av[it].z >= 0.f);
            const unsigned b3 = __ballot_sync(0xffffffffu, av[it].w >= 0.f);
            if (lane == it * 4    ) mymask = b0;
            if (lane == it * 4 + 1) mymask = b1;
            if (lane == it * 4 + 2) mymask = b2;
            if (lane == it * 4 + 3) mymask = b3;
        }
        const int cnt = __popc(mymask);
        int incl = cnt;
#pragma unroll
        for (int o = 1; o < 32; o <<= 1) {
            int v = __shfl_up_sync(0xffffffffu, incl, o);
            if (lane >= o) incl += v;
        }
        if (lane == 31) S.woff[wid] = incl;
        __syncthreads();
        if (tid == 0) {
            int run = 0;
#pragma unroll
            for (int w = 0; w < 8; w++) { int t = S.woff[w]; S.woff[w] = run; run += t; }
            S.total = run;
        }
        __syncthreads();
        const int total = S.total;
        const bool ok = (total > 0) && (total <= CAP);

        if (ok && cnt) {
            int go = S.woff[wid] + incl - cnt;
            const int jbase = ((lane >> 2) * 256 + wid * 32) * 4 + (lane & 3);
            unsigned mm = mymask;
            while (mm) {
                const int k = __ffs(mm) - 1;
                mm &= mm - 1;
                S.idx[go++] = jbase + k * 4;
            }
        }
        __syncthreads();

        // ---- one-time wait for projection outputs ----
        if (tid == 0 && !S.ready) {
            while (*(volatile int*)&g_done != NPROJ) __nanosleep(64);
            S.ready = 1;
        }
        __syncthreads();
        __threadfence();

        // ---- phase B ----
        if (ok) {
            const float f1i = g_f1[row];
            if (wid == 0) {
                float lm = -INFINITY;
                for (int e = lane; e < total; e += 32) {
                    float s = f1i + g_f2[S.idx[e]];
                    s = s > 0.f ? s : ALPHA * s;
                    S.wt[e] = s;
                    lm = fmaxf(lm, s);
                }
#pragma unroll
                for (int o = 16; o > 0; o >>= 1)
                    lm = fmaxf(lm, __shfl_xor_sync(0xffffffffu, lm, o));
                float ls = 0.f;
                for (int e = lane; e < total; e += 32) {
                    const float w = expf(S.wt[e] - lm);
                    S.wt[e] = w;
                    ls += w;
                }
#pragma unroll
                for (int o = 16; o > 0; o >>= 1)
                    ls += __shfl_xor_sync(0xffffffffu, ls, o);
                if (lane == 0) S.Sv = ls;
            }
            __syncthreads();

            // gather: 4 groups x 64 features, 2-way unrolled
            const int g = tid >> 6, f = tid & 63;
            float acc0 = 0.f, acc1 = 0.f;
            for (int e = g; e < total; e += 8) {
                acc0 = fmaf(S.wt[e], g_fts[(size_t)S.idx[e] * FOUT + f], acc0);
                if (e + 4 < total)
                    acc1 = fmaf(S.wt[e + 4], g_fts[(size_t)S.idx[e + 4] * FOUT + f], acc1);
            }
            S.part[g * FOUT + f] = acc0 + acc1;
            __syncthreads();

            if (tid < FOUT) {
                float v = (S.part[tid] + S.part[FOUT + tid] +
                           S.part[2 * FOUT + tid] + S.part[3 * FOUT + tid]) / S.Sv
                          + __ldg(&bias[tid]);
                out[(size_t)row * FOUT + tid] = v > 0.f ? v : expm1f(v);
            }
        } else {
            // ---- exact block-wide streaming fallback (P ~ 0) ----
            const float f1i = g_f1[row];
            const float* __restrict__ adjs = adj + (size_t)row * N;
            float lm = -INFINITY;
            for (int j = tid; j < N; j += 256) {
                float s = f1i + g_f2[j];
                s = s > 0.f ? s : ALPHA * s;
                lm = fmaxf(lm, s + adjs[j]);
            }
#pragma unroll
            for (int o = 16; o > 0; o >>= 1)
                lm = fmaxf(lm, __shfl_xor_sync(0xffffffffu, lm, o));
            if (lane == 0) S.red[wid] = lm;
            __syncthreads();
            if (tid == 0) {
                float m = S.red[0];
#pragma unroll
                for (int w = 1; w < 8; w++) m = fmaxf(m, S.red[w]);
                S.mv = m;
            }
            __syncthreads();
            const float m = S.mv;
            float ls = 0.f;
            for (int j = tid; j < N; j += 256) {
                float s = f1i + g_f2[j];
                s = s > 0.f ? s : ALPHA * s;
                ls += expf(s + adjs[j] - m);
            }
#pragma unroll
            for (int o = 16; o > 0; o >>= 1)
                ls += __shfl_xor_sync(0xffffffffu, ls, o);
            if (lane == 0) S.red[wid] = ls;
            __syncthreads();
            if (tid == 0) {
                float Sv = 0.f;
#pragma unroll
                for (int w = 0; w < 8; w++) Sv += S.red[w];
                S.Sv = Sv;
            }
            __syncthreads();
            if (tid < FOUT) {
                const float invS = 1.0f / S.Sv;
                float acc = 0.f;
                for (int j = 0; j < N; j++) {
                    float s = f1i + g_f2[j];
                    s = s > 0.f ? s : ALPHA * s;
                    const float w = expf(s + adjs[j] - m);
                    if (w > 0.f)
                        acc = fmaf(w, g_fts[(size_t)j * FOUT + tid], acc);
                }
                float v = acc * invS + __ldg(&bias[tid]);
                out[(size_t)row * FOUT + tid] = v > 0.f ? v : expm1f(v);
            }
        }
        __syncthreads();
    }

    // ---- self-cleaning flags for graph replay ----
    if (tid == 0) {
        const int v = atomicAdd(&g_fin, 1);
        if (v == NSCANB - 1) {      // all scan blocks finished all rows
            g_done = 0;
            g_fin  = 0;
            g_row  = 0;
        }
    }
}

// ---------------- launcher ---------------------------------------------------
extern "C" void kernel_launch(void* const* d_in, const int* in_sizes, int n_in,
                              void* d_out, int out_size) {
    const float* x    = (const float*)d_in[0];
    const float* adj  = (const float*)d_in[1];
    const float* W    = (const float*)d_in[2];
    const float* a1   = (const float*)d_in[3];
    const float* b1   = (const float*)d_in[4];
    const float* a2   = (const float*)d_in[5];
    const float* b2   = (const float*)d_in[6];
    const float* bias = (const float*)d_in[7];
    float* out = (float*)d_out;

    k_main<<<NBLK, 256>>>(x, W, adj, a1, b1, a2, b2, bias, out);
}

// round 10
// speedup vs baseline: 1.4925x; 1.4925x over previous
#include <cuda_runtime.h>
#include <math.h>
#include <stdint.h>

#define N      8192
#define FIN    256
#define FOUT   64
#define ALPHA  0.2f

#define NPROJ  128
#define TR     64
#define KC     32
#define NCH    (FIN / KC)
#define CAPG   128          // global neighbor capacity/row (E=32)

// ---------------- scratch (static __device__, allocation-free) --------------
__device__ __align__(16) static float g_fts[N * FOUT];
__device__ __align__(16) static float g_f1[N];
__device__ __align__(16) static float g_f2[N];
__device__ __align__(16) static int   g_idx[N * CAPG];   // 4 MB CSR indices
__device__ __align__(16) static int   g_cnt[N];

// smem union for k_pa: proj tile vs tiny scan state
struct ProjS {
    float xs[TR][KC + 1];
    float ws[KC * FOUT];
};
struct ScanA {
    int woff[8];
    int total;
};

// ============================================================================
// Launch 1: proj blocks (bid<NPROJ) + tail-free adjacency scan (bid>=NPROJ).
// Scan blocks have ZERO dependency on proj — no flags, no spins.
// ============================================================================
__global__ __launch_bounds__(256) void k_pa(
        const float* __restrict__ x,   const float* __restrict__ W,
        const float* __restrict__ adj,
        const float* __restrict__ a1,  const float* __restrict__ b1,
        const float* __restrict__ a2,  const float* __restrict__ b2) {
    __shared__ __align__(16) char smem_raw[sizeof(ProjS)];
    const int tid  = threadIdx.x;
    const int lane = tid & 31;
    const int wid  = tid >> 5;

    if (blockIdx.x < NPROJ) {
        // ========================= projection role ==========================
        ProjS& S = *reinterpret_cast<ProjS*>(smem_raw);
        const int row0 = blockIdx.x * TR;
        const int fg = tid & 15, rg = tid >> 4;
        const int f0 = fg * 4,   r0 = rg * 4;
        const int xk = tid & 31, xr0 = tid >> 5;
        const float4* __restrict__ W4 = (const float4*)W;

        float acc[4][4] = {};
#pragma unroll
        for (int c = 0; c < NCH; c++) {
            const int kc = c * KC;
            __syncthreads();
#pragma unroll
            for (int i = 0; i < 8; i++)
                S.xs[xr0 + 8 * i][xk] = x[(size_t)(row0 + xr0 + 8 * i) * FIN + kc + xk];
            {
                float4* ws4 = (float4*)S.ws;
#pragma unroll
                for (int i = 0; i < 2; i++)
                    ws4[tid + i * 256] = W4[kc * 16 + tid + i * 256];
            }
            __syncthreads();
#pragma unroll
            for (int k = 0; k < KC; k++) {
                const float4 wv = *(const float4*)&S.ws[k * FOUT + f0];
                float xr[4];
#pragma unroll
                for (int r = 0; r < 4; r++) xr[r] = S.xs[r0 + r][k];
                const float wf[4] = {wv.x, wv.y, wv.z, wv.w};
#pragma unroll
                for (int r = 0; r < 4; r++)
#pragma unroll
                    for (int j = 0; j < 4; j++)
                        acc[r][j] = fmaf(xr[r], wf[j], acc[r][j]);
            }
        }

#pragma unroll
        for (int r = 0; r < 4; r++) {
            float4 v = make_float4(acc[r][0], acc[r][1], acc[r][2], acc[r][3]);
            *(float4*)&g_fts[(size_t)(row0 + r0 + r) * FOUT + f0] = v;
        }

        const float4 a1v = *(const float4*)&a1[f0];
        const float4 a2v = *(const float4*)&a2[f0];
        float p1[4], p2[4];
#pragma unroll
        for (int r = 0; r < 4; r++) {
            p1[r] = acc[r][0]*a1v.x + acc[r][1]*a1v.y + acc[r][2]*a1v.z + acc[r][3]*a1v.w;
            p2[r] = acc[r][0]*a2v.x + acc[r][1]*a2v.y + acc[r][2]*a2v.z + acc[r][3]*a2v.w;
        }
#pragma unroll
        for (int o = 1; o < 16; o <<= 1) {
#pragma unroll
            for (int r = 0; r < 4; r++) {
                p1[r] += __shfl_xor_sync(0xffffffffu, p1[r], o);
                p2[r] += __shfl_xor_sync(0xffffffffu, p2[r], o);
            }
        }
        if (fg == 0) {
            const float bb1 = __ldg(b1), bb2 = __ldg(b2);
#pragma unroll
            for (int r = 0; r < 4; r++) {
                g_f1[row0 + r0 + r] = p1[r] + bb1;
                g_f2[row0 + r0 + r] = p2[r] + bb2;
            }
        }
        return;
    }

    // ==================== tail-free adjacency scan role =====================
    ScanA& S = *reinterpret_cast<ScanA*>(smem_raw);
    const int row = blockIdx.x - NPROJ;
    const float4* __restrict__ adjr = (const float4*)(adj + (size_t)row * N);

    // batched full-row stream: 8 x float4 per thread (32KB per block)
    float4 av[8];
#pragma unroll
    for (int it = 0; it < 8; it++)
        av[it] = __ldcs(&adjr[it * 256 + tid]);

    // ballot mask: lane L holds ballot word for (it = L>>2, comp = L&3)
    unsigned mymask = 0;
#pragma unroll
    for (int it = 0; it < 8; it++) {
        const unsigned b0 = __ballot_sync(0xffffffffu, av[it].x >= 0.f);
        const unsigned b1 = __ballot_sync(0xffffffffu, av[it].y >= 0.f);
        const unsigned b2 = __ballot_sync(0xffffffffu, av[it].z >= 0.f);
        const unsigned b3 = __ballot_sync(0xffffffffu, av[it].w >= 0.f);
        if (lane == it * 4    ) mymask = b0;
        if (lane == it * 4 + 1) mymask = b1;
        if (lane == it * 4 + 2) mymask = b2;
        if (lane == it * 4 + 3) mymask = b3;
    }
    const int cnt = __popc(mymask);

    int incl = cnt;
#pragma unroll
    for (int o = 1; o < 32; o <<= 1) {
        int v = __shfl_up_sync(0xffffffffu, incl, o);
        if (lane >= o) incl += v;
    }
    if (lane == 31) S.woff[wid] = incl;
    __syncthreads();
    if (tid == 0) {
        int run = 0;
#pragma unroll
        for (int w = 0; w < 8; w++) { int t = S.woff[w]; S.woff[w] = run; run += t; }
        S.total = run;
        g_cnt[row] = run;
    }
    __syncthreads();

    if (S.total <= CAPG && cnt) {
        int go = row * CAPG + S.woff[wid] + incl - cnt;
        const int jbase = ((lane >> 2) * 256 + wid * 32) * 4 + (lane & 3);
        unsigned mm = mymask;
        while (mm) {
            const int k = __ffs(mm) - 1;
            mm &= mm - 1;
            g_idx[go++] = jbase + k * 4;
        }
    }
}

// ============================================================================
// Launch 2: finish. Warp per row: scores -> softmax -> fts gather -> elu.
// ============================================================================
__global__ __launch_bounds__(256) void k_b(const float* __restrict__ adj,
                                           const float* __restrict__ bias,
                                           float* __restrict__ out) {
    __shared__ float s_wt[8][CAPG];
    __shared__ int   s_ix[8][CAPG];

    const int lane = threadIdx.x & 31;
    const int wid  = threadIdx.x >> 5;
    const int row  = blockIdx.x * 8 + wid;
    const int cnt  = g_cnt[row];
    const float f1i = g_f1[row];
    const float bias0 = __ldg(&bias[lane]);
    const float bias1 = __ldg(&bias[lane + 32]);

    if (cnt > 0 && cnt <= CAPG) {
        // scores + warp softmax (<=4 entries per lane)
        int   myi[4];
        float myw[4];
        float lm = -INFINITY;
#pragma unroll
        for (int r = 0; r < 4; r++) {
            const int e = lane + r * 32;
            if (e < cnt) {
                myi[r] = g_idx[row * CAPG + e];
                float s = f1i + g_f2[myi[r]];
                s = s > 0.f ? s : ALPHA * s;
                myw[r] = s;
                lm = fmaxf(lm, s);
            }
        }
#pragma unroll
        for (int o = 16; o > 0; o >>= 1)
            lm = fmaxf(lm, __shfl_xor_sync(0xffffffffu, lm, o));
        float ls = 0.f;
#pragma unroll
        for (int r = 0; r < 4; r++) {
            const int e = lane + r * 32;
            if (e < cnt) {
                myw[r] = expf(myw[r] - lm);
                ls += myw[r];
            }
        }
#pragma unroll
        for (int o = 16; o > 0; o >>= 1)
            ls += __shfl_xor_sync(0xffffffffu, ls, o);

#pragma unroll
        for (int r = 0; r < 4; r++) {
            const int e = lane + r * 32;
            if (e < cnt) {
                s_wt[wid][e] = myw[r];
                s_ix[wid][e] = myi[r];
            }
        }
        __syncwarp();

        // gather, 2-way unrolled (independent load chains)
        const float invS = 1.0f / ls;
        float acc0 = 0.f, acc1 = 0.f, acc2 = 0.f, acc3 = 0.f;
        int e = 0;
        for (; e + 1 < cnt; e += 2) {
            const float w0 = s_wt[wid][e],     w1 = s_wt[wid][e + 1];
            const float* f0 = &g_fts[(size_t)s_ix[wid][e]     * FOUT];
            const float* f1 = &g_fts[(size_t)s_ix[wid][e + 1] * FOUT];
            acc0 = fmaf(w0, f0[lane],      acc0);
            acc1 = fmaf(w0, f0[lane + 32], acc1);
            acc2 = fmaf(w1, f1[lane],      acc2);
            acc3 = fmaf(w1, f1[lane + 32], acc3);
        }
        if (e < cnt) {
            const float w0 = s_wt[wid][e];
            const float* f0 = &g_fts[(size_t)s_ix[wid][e] * FOUT];
            acc0 = fmaf(w0, f0[lane],      acc0);
            acc1 = fmaf(w0, f0[lane + 32], acc1);
        }
        float v0 = (acc0 + acc2) * invS + bias0;
        float v1 = (acc1 + acc3) * invS + bias1;
        out[(size_t)row * FOUT + lane]      = v0 > 0.f ? v0 : expm1f(v0);
        out[(size_t)row * FOUT + lane + 32] = v1 > 0.f ? v1 : expm1f(v1);
    } else {
        // exact warp-scoped streaming fallback (P ~ 1e-10 per row)
        const float* __restrict__ adjs = adj + (size_t)row * N;
        float lm = -INFINITY;
        for (int j = lane; j < N; j += 32) {
            float s = f1i + g_f2[j];
            s = s > 0.f ? s : ALPHA * s;
            lm = fmaxf(lm, s + adjs[j]);
        }
#pragma unroll
        for (int o = 16; o > 0; o >>= 1)
            lm = fmaxf(lm, __shfl_xor_sync(0xffffffffu, lm, o));
        float ls = 0.f;
        for (int j = lane; j < N; j += 32) {
            float s = f1i + g_f2[j];
            s = s > 0.f ? s : ALPHA * s;
            ls += expf(s + adjs[j] - lm);
        }
#pragma unroll
        for (int o = 16; o > 0; o >>= 1)
            ls += __shfl_xor_sync(0xffffffffu, ls, o);
        const float invS = 1.0f / ls;
        float acc0 = 0.f, acc1 = 0.f;
        for (int j = 0; j < N; j++) {
            float s = f1i + g_f2[j];
            s = s > 0.f ? s : ALPHA * s;
            const float w = expf(s + adjs[j] - lm);
            if (w > 0.f) {
                const float* fr = &g_fts[(size_t)j * FOUT];
                acc0 = fmaf(w, fr[lane],      acc0);
                acc1 = fmaf(w, fr[lane + 32], acc1);
            }
        }
        float v0 = acc0 * invS + bias0;
        float v1 = acc1 * invS + bias1;
        out[(size_t)row * FOUT + lane]      = v0 > 0.f ? v0 : expm1f(v0);
        out[(size_t)row * FOUT + lane + 32] = v1 > 0.f ? v1 : expm1f(v1);
    }
}

// ---------------- launcher ---------------------------------------------------
extern "C" void kernel_launch(void* const* d_in, const int* in_sizes, int n_in,
                              void* d_out, int out_size) {
    const float* x    = (const float*)d_in[0];
    const float* adj  = (const float*)d_in[1];
    const float* W    = (const float*)d_in[2];
    const float* a1   = (const float*)d_in[3];
    const float* b1   = (const float*)d_in[4];
    const float* a2   = (const float*)d_in[5];
    const float* b2   = (const float*)d_in[6];
    const float* bias = (const float*)d_in[7];
    float* out = (float*)d_out;

    k_pa<<<NPROJ + N, 256>>>(x, W, adj, a1, b1, a2, b2);
    k_b <<<N / 8, 256>>>(adj, bias, out);
}